// round 1
// baseline (speedup 1.0000x reference)
#include <cuda_runtime.h>
#include <math.h>

#define B 64
#define S 2048
#define H 512
#define E 1024   // 2*H
#define NCHUNK 4 // context s-split

// Scratch (allocation-free rule: __device__ globals)
__device__ float g_proj_dec[B * H];
__device__ float g_scores[B * S];
__device__ float g_ctx_part[NCHUNK][B * E];

// ---------------------------------------------------------------------------
// Kernel 1: proj_dec[b,h] = sum_d dec[b,d] * W_d[d,h]   (64x512x512, tiny)
// ---------------------------------------------------------------------------
__global__ __launch_bounds__(512) void proj_dec_kernel(
    const float* __restrict__ dec, const float* __restrict__ Wd)
{
    __shared__ float dsh[H];
    int b = blockIdx.x;
    int h = threadIdx.x;
    dsh[h] = dec[b * H + h];
    __syncthreads();
    float sum = 0.f;
#pragma unroll 8
    for (int d = 0; d < H; ++d)
        sum += dsh[d] * Wd[d * H + h];
    g_proj_dec[b * H + h] = sum;
}

// ---------------------------------------------------------------------------
// Kernel 2: fused scores GEMM.
// scores[b,s] = sum_h v[h] * tanh( (enc[b,s,:] @ W_h)[h] + proj_dec[b,h] )
// M = B*S = 131072 rows, K = E = 1024, N = H = 512.
// Tiling: BM=64 rows/block, BN=128 col-tile (4 passes), BK=16.
// 256 threads (16x16), 4x8 micro-tile. tanh*v row-reduction epilogue per tile.
// ---------------------------------------------------------------------------
#define BM 64
#define BN 128
#define BK 16
#define TM 4
#define TN 8

__global__ __launch_bounds__(256) void scores_kernel(
    const float* __restrict__ enc, const float* __restrict__ Wh,
    const float* __restrict__ v)
{
    __shared__ float As[BK][BM];
    __shared__ float Wsm[BK][BN];
    __shared__ float red[BM][16];

    const int tid = threadIdx.x;
    const int tx = tid & 15;
    const int ty = tid >> 4;
    const int row0 = blockIdx.x * BM;   // global row (= b*S + s0, BM | S)
    const int b = row0 / S;

    const float* Arow = enc + (size_t)row0 * E;

    float score_acc[TM] = {0.f, 0.f, 0.f, 0.f};

    for (int n0 = 0; n0 < H; n0 += BN) {
        float acc[TM][TN];
#pragma unroll
        for (int i = 0; i < TM; i++)
#pragma unroll
            for (int j = 0; j < TN; j++) acc[i][j] = 0.f;

        for (int k0 = 0; k0 < E; k0 += BK) {
            // Load A tile: BM x BK   (tid -> (row, k))
            {
                int k = tid & (BK - 1);
                int r = tid >> 4;        // 0..15
#pragma unroll
                for (int rr = 0; rr < BM; rr += 16)
                    As[k][r + rr] = Arow[(size_t)(r + rr) * E + k0 + k];
            }
            // Load W tile: BK x BN  (coalesced over n)
            {
                int n = tid & (BN - 1);
                int k = tid >> 7;        // 0..1
#pragma unroll
                for (int kk = 0; kk < BK; kk += 2)
                    Wsm[k + kk][n] = Wh[(size_t)(k0 + k + kk) * H + n0 + n];
            }
            __syncthreads();

#pragma unroll
            for (int k = 0; k < BK; ++k) {
                float a[TM], w[TN];
#pragma unroll
                for (int i = 0; i < TM; i++) a[i] = As[k][ty * TM + i];
#pragma unroll
                for (int j = 0; j < TN; j++) w[j] = Wsm[k][tx * TN + j];
#pragma unroll
                for (int i = 0; i < TM; i++)
#pragma unroll
                    for (int j = 0; j < TN; j++)
                        acc[i][j] += a[i] * w[j];
            }
            __syncthreads();
        }

        // Epilogue: tanh(acc + proj_dec) * v, accumulate per-row partial score
#pragma unroll
        for (int j = 0; j < TN; j++) {
            int n = n0 + tx * TN + j;
            float pdv = g_proj_dec[b * H + n];
            float vv  = v[n];
#pragma unroll
            for (int i = 0; i < TM; i++)
                score_acc[i] += tanhf(acc[i][j] + pdv) * vv;
        }
        __syncthreads();
    }

    // Cross-thread (tx) row reduction
#pragma unroll
    for (int i = 0; i < TM; i++) red[ty * TM + i][tx] = score_acc[i];
    __syncthreads();
    if (tid < BM) {
        float s = 0.f;
#pragma unroll
        for (int t = 0; t < 16; t++) s += red[tid][t];
        g_scores[row0 + tid] = s;
    }
}

// ---------------------------------------------------------------------------
// Kernel 3: mask + softmax over S per batch row. Writes attn to d_out region.
// ---------------------------------------------------------------------------
__global__ __launch_bounds__(256) void softmax_kernel(
    const int* __restrict__ mask, float* __restrict__ attn)
{
    __shared__ float buf[S];
    __shared__ float redv[256];
    const int b = blockIdx.x;
    const int tid = threadIdx.x;

    float mx = -INFINITY;
    for (int s = tid; s < S; s += 256) {
        float sc = (mask[b * S + s] == 0) ? -10000.0f : g_scores[b * S + s];
        buf[s] = sc;
        mx = fmaxf(mx, sc);
    }
    redv[tid] = mx;
    __syncthreads();
    for (int st = 128; st > 0; st >>= 1) {
        if (tid < st) redv[tid] = fmaxf(redv[tid], redv[tid + st]);
        __syncthreads();
    }
    mx = redv[0];
    __syncthreads();

    float sum = 0.f;
    for (int s = tid; s < S; s += 256) {
        float e = __expf(buf[s] - mx);
        buf[s] = e;
        sum += e;
    }
    redv[tid] = sum;
    __syncthreads();
    for (int st = 128; st > 0; st >>= 1) {
        if (tid < st) redv[tid] += redv[tid + st];
        __syncthreads();
    }
    float inv = 1.0f / redv[0];
    for (int s = tid; s < S; s += 256)
        attn[b * S + s] = buf[s] * inv;
}

// ---------------------------------------------------------------------------
// Kernel 4: context partials. grid (B, NCHUNK); each block sums 512 s values.
// ---------------------------------------------------------------------------
__global__ __launch_bounds__(256) void context_part_kernel(
    const float* __restrict__ enc, const float* __restrict__ attn)
{
    __shared__ float w[S / NCHUNK];
    const int b = blockIdx.x;
    const int chunk = blockIdx.y;
    const int tid = threadIdx.x;
    const int s0 = chunk * (S / NCHUNK);

    for (int s = tid; s < S / NCHUNK; s += 256)
        w[s] = attn[b * S + s0 + s];
    __syncthreads();

    const float4* e4 = (const float4*)(enc + ((size_t)b * S + s0) * E);
    float4 c = make_float4(0.f, 0.f, 0.f, 0.f);
#pragma unroll 4
    for (int s = 0; s < S / NCHUNK; ++s) {
        float4 ev = e4[(size_t)s * (E / 4) + tid];
        float ww = w[s];
        c.x += ww * ev.x; c.y += ww * ev.y;
        c.z += ww * ev.z; c.w += ww * ev.w;
    }
    ((float4*)(&g_ctx_part[chunk][b * E]))[tid] = c;
}

// ---------------------------------------------------------------------------
// Kernel 5: reduce context partials into d_out.
// ---------------------------------------------------------------------------
__global__ __launch_bounds__(256) void context_reduce_kernel(float* __restrict__ ctx)
{
    const int b = blockIdx.x;
    const int tid = threadIdx.x;
    float4 c = make_float4(0.f, 0.f, 0.f, 0.f);
#pragma unroll
    for (int ch = 0; ch < NCHUNK; ++ch) {
        float4 p = ((const float4*)(&g_ctx_part[ch][b * E]))[tid];
        c.x += p.x; c.y += p.y; c.z += p.z; c.w += p.w;
    }
    ((float4*)(ctx + b * E))[tid] = c;
}

// ---------------------------------------------------------------------------
extern "C" void kernel_launch(void* const* d_in, const int* in_sizes, int n_in,
                              void* d_out, int out_size)
{
    const float* dec  = (const float*)d_in[0];  // (B, H)
    const float* enc  = (const float*)d_in[1];  // (B, S, 2H)
    const int*   mask = (const int*)  d_in[2];  // (B, S)
    const float* Wh   = (const float*)d_in[3];  // (2H, H)
    const float* Wd   = (const float*)d_in[4];  // (H, H)
    const float* v    = (const float*)d_in[5];  // (H,)

    float* out  = (float*)d_out;
    float* ctx  = out;             // (B, 2H) = 65536 floats
    float* attn = out + B * E;     // (B, S)  = 131072 floats

    proj_dec_kernel<<<B, H>>>(dec, Wd);
    scores_kernel<<<(B * S) / BM, 256>>>(enc, Wh, v);
    softmax_kernel<<<B, 256>>>(mask, attn);
    dim3 gctx(B, NCHUNK);
    context_part_kernel<<<gctx, 256>>>(enc, attn);
    context_reduce_kernel<<<B, 256>>>(ctx);
}

// round 3
// speedup vs baseline: 4.6219x; 4.6219x over previous
#include <cuda_runtime.h>
#include <cuda_bf16.h>
#include <cstdint>
#include <math.h>

#define B 64
#define S 2048
#define H 512
#define E 1024   // 2*H
#define NCHUNK 8

// ---------------------------------------------------------------------------
// Device scratch (allocation-free rule)
// ---------------------------------------------------------------------------
__device__ float g_proj_dec[B * H];
__device__ float g_scores_part[2][B * S];
__device__ float g_ctx_part[NCHUNK][B * E];
__device__ __nv_bfloat16 g_Whi[E * H];   // [k][n] hi(W_h)
__device__ __nv_bfloat16 g_Wlo[E * H];   // [k][n] lo(W_h)

// ---------------------------------------------------------------------------
// Helpers
// ---------------------------------------------------------------------------
__device__ __forceinline__ uint32_t smem_u32(const void* p) {
    uint32_t a;
    asm("{ .reg .u64 t; cvta.to.shared.u64 t, %1; cvt.u32.u64 %0, t; }" : "=r"(a) : "l"(p));
    return a;
}
__device__ __forceinline__ void cp16(uint32_t dst, const void* src) {
    asm volatile("cp.async.cg.shared.global [%0], [%1], 16;" :: "r"(dst), "l"(src));
}
__device__ __forceinline__ void cp_commit() {
    asm volatile("cp.async.commit_group;" ::: "memory");
}
__device__ __forceinline__ void cp_wait1() {
    asm volatile("cp.async.wait_group 1;" ::: "memory");
}
__device__ __forceinline__ void ldsm_x4(uint32_t addr, uint32_t* r) {
    asm volatile("ldmatrix.sync.aligned.m8n8.x4.shared.b16 {%0,%1,%2,%3}, [%4];"
                 : "=r"(r[0]), "=r"(r[1]), "=r"(r[2]), "=r"(r[3]) : "r"(addr));
}
__device__ __forceinline__ void ldsm_x4_t(uint32_t addr, uint32_t* r) {
    asm volatile("ldmatrix.sync.aligned.m8n8.x4.trans.shared.b16 {%0,%1,%2,%3}, [%4];"
                 : "=r"(r[0]), "=r"(r[1]), "=r"(r[2]), "=r"(r[3]) : "r"(addr));
}
__device__ __forceinline__ void mma_bf16(float* c, const uint32_t* a, uint32_t b0, uint32_t b1) {
    asm volatile("mma.sync.aligned.m16n8k16.row.col.f32.bf16.bf16.f32 "
                 "{%0,%1,%2,%3}, {%4,%5,%6,%7}, {%8,%9}, {%0,%1,%2,%3};"
                 : "+f"(c[0]), "+f"(c[1]), "+f"(c[2]), "+f"(c[3])
                 : "r"(a[0]), "r"(a[1]), "r"(a[2]), "r"(a[3]), "r"(b0), "r"(b1));
}
__device__ __forceinline__ void f2bf_hilo(float x, uint16_t& hi, uint16_t& lo) {
    __nv_bfloat16 h = __float2bfloat16(x);
    float r = x - __bfloat162float(h);
    __nv_bfloat16 l = __float2bfloat16(r);
    hi = *reinterpret_cast<uint16_t*>(&h);
    lo = *reinterpret_cast<uint16_t*>(&l);
}

// ---------------------------------------------------------------------------
// Kernel 0: elementwise split W_h -> hi/lo bf16 ([k][n] layout preserved)
// ---------------------------------------------------------------------------
__global__ __launch_bounds__(256) void conv_w_kernel(const float* __restrict__ Wh)
{
    int i = blockIdx.x * 256 + threadIdx.x;
    float x = Wh[i];
    uint16_t hi, lo;
    f2bf_hilo(x, hi, lo);
    g_Whi[i] = *reinterpret_cast<__nv_bfloat16*>(&hi);
    g_Wlo[i] = *reinterpret_cast<__nv_bfloat16*>(&lo);
}

// ---------------------------------------------------------------------------
// Kernel 1: proj_dec (tiny)
// ---------------------------------------------------------------------------
__global__ __launch_bounds__(512) void proj_dec_kernel(
    const float* __restrict__ dec, const float* __restrict__ Wd)
{
    __shared__ float dsh[H];
    int b = blockIdx.x;
    int h = threadIdx.x;
    dsh[h] = dec[b * H + h];
    __syncthreads();
    float sum = 0.f;
#pragma unroll 8
    for (int d = 0; d < H; ++d)
        sum += dsh[d] * Wd[d * H + h];
    g_proj_dec[b * H + h] = sum;
}

// ---------------------------------------------------------------------------
// Kernel 2: scores via mma.sync bf16 (3-term fp32 emulation) + tanh·v epilogue
// Block tile: 128(M) x 256(N), BK=32, 8 warps (2x4), warp tile 64x64.
// Grid: (2, 1024). blockIdx.x = n-pass (0/1), blockIdx.y = row block.
// ---------------------------------------------------------------------------
#define KSTEPS 32   // 1024 / 32

// Dynamic SMEM layout (bytes)
#define SW_BUF   0         // 3 x 32768 (hi 16K | lo 16K)
#define SA_BUF   98304     // 2 x 16384 (hi 8K  | lo 8K)
#define S_PD     131072    // 256 f32
#define S_V      132096    // 256 f32
#define S_RED    133120    // 128*4 f32 = 2KB
#define SM_TOT   135168

__global__ void __launch_bounds__(256) scores_mma_kernel(
    const float* __restrict__ enc, const float* __restrict__ v)
{
    extern __shared__ char smem[];
    const uint32_t sb = smem_u32(smem);
    const int tid  = threadIdx.x;
    const int lane = tid & 31;
    const int warp = tid >> 5;
    const int wm   = warp >> 2;        // 0..1
    const int wn   = warp & 3;         // 0..3
    const int ny   = blockIdx.x;       // 0..1 (n-pass)
    const int row0 = blockIdx.y * 128;
    const int b    = row0 >> 11;       // S = 2048

    float* pd_sh = (float*)(smem + S_PD);
    float* v_sh  = (float*)(smem + S_V);
    float* red   = (float*)(smem + S_RED);
    pd_sh[tid] = g_proj_dec[b * H + ny * 256 + tid];
    v_sh[tid]  = v[ny * 256 + tid];

    // A (enc) load mapping: 2 threads per row, 16 k-elems each
    const int am = tid >> 1;           // 0..127
    const int ap = tid & 1;            // k half (0/1 -> 16 elems)
    const float* aptr = enc + (size_t)(row0 + am) * E + ap * 16;

    // W cp.async mapping: 4 chunks of 16B per thread per (hi|lo)
    const __nv_bfloat16* whbase = g_Whi + ny * 256;
    const __nv_bfloat16* wlbase = g_Wlo + ny * 256;

    float c[4][8][4];
#pragma unroll
    for (int mt = 0; mt < 4; mt++)
#pragma unroll
        for (int j = 0; j < 8; j++)
#pragma unroll
            for (int q = 0; q < 4; q++) c[mt][j][q] = 0.f;

    uint4 pref[4];

    // ---- lambdas ----
    auto issueW = [&](int st) {
        uint32_t wb = sb + SW_BUF + (uint32_t)(st % 3) * 32768u;
        const __nv_bfloat16* bh = whbase + (size_t)(st * 32) * H;
        const __nv_bfloat16* bl = wlbase + (size_t)(st * 32) * H;
#pragma unroll
        for (int it = 0; it < 4; it++) {
            int idx = tid + it * 256;
            int k = idx >> 5;          // 0..31
            int g = idx & 31;          // 16B group (8 bf16)
            uint32_t off = (uint32_t)(k * 512 + ((g ^ (k & 7)) << 4));
            cp16(wb + off,          bh + (size_t)k * H + g * 8);
            cp16(wb + 16384 + off,  bl + (size_t)k * H + g * 8);
        }
    };
    auto ldA = [&](int st) {
        const uint4* p = (const uint4*)(aptr + st * 32);
#pragma unroll
        for (int i = 0; i < 4; i++) pref[i] = p[i];
    };
    auto cvtStsA = [&](int st) {
        char* ab = smem + SA_BUF + (st & 1) * 16384;
#pragma unroll
        for (int i = 0; i < 4; i++) {
            float4 f = *(float4*)&pref[i];
            uint16_t h0, h1, h2, h3, l0, l1, l2, l3;
            f2bf_hilo(f.x, h0, l0);
            f2bf_hilo(f.y, h1, l1);
            f2bf_hilo(f.z, h2, l2);
            f2bf_hilo(f.w, h3, l3);
            uint2 hv = make_uint2((uint32_t)h0 | ((uint32_t)h1 << 16),
                                  (uint32_t)h2 | ((uint32_t)h3 << 16));
            uint2 lv = make_uint2((uint32_t)l0 | ((uint32_t)l1 << 16),
                                  (uint32_t)l2 | ((uint32_t)l3 << 16));
            int g = ap * 2 + (i >> 1);   // 16B group within 64B row
            uint32_t off = (uint32_t)(am * 64 + ((g ^ ((am >> 1) & 3)) << 4) + (i & 1) * 8);
            *(uint2*)(ab + off)        = hv;
            *(uint2*)(ab + 8192 + off) = lv;
        }
    };
    auto doMMA = [&](int st) {
        uint32_t ab = sb + SA_BUF + (uint32_t)(st & 1) * 16384u;
        uint32_t wb = sb + SW_BUF + (uint32_t)(st % 3) * 32768u;
#pragma unroll
        for (int ks = 0; ks < 2; ks++) {
            uint32_t ahi[4][4], alo[4][4], bhi[4][4], blo[4][4];
            const int mrb = wm * 64 + (lane & 15);
            const int kg  = ks * 2 + (lane >> 4);
#pragma unroll
            for (int mt = 0; mt < 4; mt++) {
                int m = mrb + mt * 16;
                uint32_t off = (uint32_t)(m * 64 + ((kg ^ ((m >> 1) & 3)) << 4));
                ldsm_x4(ab + off,        ahi[mt]);
                ldsm_x4(ab + 8192 + off, alo[mt]);
            }
            const int kr = ks * 16 + (lane & 7) + ((lane >> 3) & 1) * 8;
#pragma unroll
            for (int jj = 0; jj < 4; jj++) {
                int ng = wn * 8 + jj * 2 + (lane >> 4);
                uint32_t off = (uint32_t)(kr * 512 + ((ng ^ (kr & 7)) << 4));
                ldsm_x4_t(wb + off,         bhi[jj]);
                ldsm_x4_t(wb + 16384 + off, blo[jj]);
            }
#pragma unroll
            for (int mt = 0; mt < 4; mt++)
#pragma unroll
                for (int j = 0; j < 8; j++) {
                    uint32_t b0h = bhi[j >> 1][(j & 1) * 2];
                    uint32_t b1h = bhi[j >> 1][(j & 1) * 2 + 1];
                    uint32_t b0l = blo[j >> 1][(j & 1) * 2];
                    uint32_t b1l = blo[j >> 1][(j & 1) * 2 + 1];
                    mma_bf16(c[mt][j], ahi[mt], b0h, b1h);  // Ah*Wh
                    mma_bf16(c[mt][j], alo[mt], b0h, b1h);  // Al*Wh
                    mma_bf16(c[mt][j], ahi[mt], b0l, b1l);  // Ah*Wl
                }
        }
    };

    // ---- prologue ----
    issueW(0); cp_commit();
    issueW(1); cp_commit();
    ldA(0);
    cvtStsA(0);
    cp_wait1();
    __syncthreads();

    // ---- main loop ----
    for (int i = 0; i < KSTEPS; i++) {
        const bool more = (i + 1 < KSTEPS);
        if (more) ldA(i + 1);
        if (i + 2 < KSTEPS) issueW(i + 2);
        cp_commit();                       // one group per iter (may be empty)
        doMMA(i);
        if (more) {
            cvtStsA(i + 1);
            cp_wait1();
            __syncthreads();
        }
    }

    // ---- epilogue: partial scores over this 256-n slice ----
    float p[4][2];
#pragma unroll
    for (int mt = 0; mt < 4; mt++) { p[mt][0] = 0.f; p[mt][1] = 0.f; }
#pragma unroll
    for (int mt = 0; mt < 4; mt++)
#pragma unroll
        for (int j = 0; j < 8; j++) {
            int nn = wn * 64 + j * 8 + ((lane & 3) << 1);
            float pd0 = pd_sh[nn], pd1 = pd_sh[nn + 1];
            float v0 = v_sh[nn], v1 = v_sh[nn + 1];
            p[mt][0] += tanhf(c[mt][j][0] + pd0) * v0 + tanhf(c[mt][j][1] + pd1) * v1;
            p[mt][1] += tanhf(c[mt][j][2] + pd0) * v0 + tanhf(c[mt][j][3] + pd1) * v1;
        }
#pragma unroll
    for (int mt = 0; mt < 4; mt++) {
        float p0 = p[mt][0], p1 = p[mt][1];
        p0 += __shfl_xor_sync(0xFFFFFFFF, p0, 1);
        p0 += __shfl_xor_sync(0xFFFFFFFF, p0, 2);
        p1 += __shfl_xor_sync(0xFFFFFFFF, p1, 1);
        p1 += __shfl_xor_sync(0xFFFFFFFF, p1, 2);
        if ((lane & 3) == 0) {
            int r = wm * 64 + mt * 16 + (lane >> 2);
            red[r * 4 + wn]       = p0;
            red[(r + 8) * 4 + wn] = p1;
        }
    }
    __syncthreads();
    if (tid < 128) {
        float s = red[tid * 4] + red[tid * 4 + 1] + red[tid * 4 + 2] + red[tid * 4 + 3];
        g_scores_part[ny][row0 + tid] = s;
    }
}

// ---------------------------------------------------------------------------
// Kernel 3: mask + softmax (sums the two n-pass partials)
// ---------------------------------------------------------------------------
__global__ __launch_bounds__(256) void softmax_kernel(
    const int* __restrict__ mask, float* __restrict__ attn)
{
    __shared__ float buf[S];
    __shared__ float redv[256];
    const int b = blockIdx.x;
    const int tid = threadIdx.x;

    float mx = -INFINITY;
    for (int s = tid; s < S; s += 256) {
        float sc = (mask[b * S + s] == 0)
                 ? -10000.0f
                 : (g_scores_part[0][b * S + s] + g_scores_part[1][b * S + s]);
        buf[s] = sc;
        mx = fmaxf(mx, sc);
    }
    redv[tid] = mx;
    __syncthreads();
    for (int st = 128; st > 0; st >>= 1) {
        if (tid < st) redv[tid] = fmaxf(redv[tid], redv[tid + st]);
        __syncthreads();
    }
    mx = redv[0];
    __syncthreads();

    float sum = 0.f;
    for (int s = tid; s < S; s += 256) {
        float e = __expf(buf[s] - mx);
        buf[s] = e;
        sum += e;
    }
    redv[tid] = sum;
    __syncthreads();
    for (int st = 128; st > 0; st >>= 1) {
        if (tid < st) redv[tid] += redv[tid + st];
        __syncthreads();
    }
    float inv = 1.0f / redv[0];
    for (int s = tid; s < S; s += 256)
        attn[b * S + s] = buf[s] * inv;
}

// ---------------------------------------------------------------------------
// Kernel 4: context partials. grid (B, NCHUNK).
// ---------------------------------------------------------------------------
__global__ __launch_bounds__(256) void context_part_kernel(
    const float* __restrict__ enc, const float* __restrict__ attn)
{
    __shared__ float w[S / NCHUNK];
    const int b = blockIdx.x;
    const int chunk = blockIdx.y;
    const int tid = threadIdx.x;
    const int s0 = chunk * (S / NCHUNK);

    for (int s = tid; s < S / NCHUNK; s += 256)
        w[s] = attn[b * S + s0 + s];
    __syncthreads();

    const float4* e4 = (const float4*)(enc + ((size_t)b * S + s0) * E);
    float4 c = make_float4(0.f, 0.f, 0.f, 0.f);
#pragma unroll 4
    for (int s = 0; s < S / NCHUNK; ++s) {
        float4 ev = e4[(size_t)s * (E / 4) + tid];
        float ww = w[s];
        c.x += ww * ev.x; c.y += ww * ev.y;
        c.z += ww * ev.z; c.w += ww * ev.w;
    }
    ((float4*)(&g_ctx_part[chunk][b * E]))[tid] = c;
}

// ---------------------------------------------------------------------------
// Kernel 5: reduce context partials into d_out.
// ---------------------------------------------------------------------------
__global__ __launch_bounds__(256) void context_reduce_kernel(float* __restrict__ ctx)
{
    const int b = blockIdx.x;
    const int tid = threadIdx.x;
    float4 c = make_float4(0.f, 0.f, 0.f, 0.f);
#pragma unroll
    for (int ch = 0; ch < NCHUNK; ++ch) {
        float4 p = ((const float4*)(&g_ctx_part[ch][b * E]))[tid];
        c.x += p.x; c.y += p.y; c.z += p.z; c.w += p.w;
    }
    ((float4*)(ctx + b * E))[tid] = c;
}

// ---------------------------------------------------------------------------
extern "C" void kernel_launch(void* const* d_in, const int* in_sizes, int n_in,
                              void* d_out, int out_size)
{
    const float* dec  = (const float*)d_in[0];  // (B, H)
    const float* enc  = (const float*)d_in[1];  // (B, S, 2H)
    const int*   mask = (const int*)  d_in[2];  // (B, S)
    const float* Wh   = (const float*)d_in[3];  // (2H, H)
    const float* Wd   = (const float*)d_in[4];  // (H, H)
    const float* v    = (const float*)d_in[5];  // (H,)

    float* out  = (float*)d_out;
    float* ctx  = out;             // (B, 2H)
    float* attn = out + B * E;     // (B, S)

    cudaFuncSetAttribute(scores_mma_kernel,
                         cudaFuncAttributeMaxDynamicSharedMemorySize, SM_TOT);

    conv_w_kernel<<<(E * H) / 256, 256>>>(Wh);
    proj_dec_kernel<<<B, H>>>(dec, Wd);
    dim3 gs(2, (B * S) / 128);
    scores_mma_kernel<<<gs, 256, SM_TOT>>>(enc, v);
    softmax_kernel<<<B, 256>>>(mask, attn);
    dim3 gctx(B, NCHUNK);
    context_part_kernel<<<gctx, 256>>>(enc, attn);
    context_reduce_kernel<<<B, 256>>>(ctx);
}

// round 4
// speedup vs baseline: 8.7023x; 1.8828x over previous
#include <cuda_runtime.h>
#include <cuda_bf16.h>
#include <cuda_fp16.h>
#include <cstdint>
#include <math.h>

#define B 64
#define S 2048
#define H 512
#define E 1024   // 2*H
#define NCHUNK 8

// ---------------------------------------------------------------------------
// Device scratch (allocation-free rule)
// ---------------------------------------------------------------------------
__device__ float g_proj_dec[B * H];
__device__ float g_scores_part[2][B * S];
__device__ float g_ctx_part[NCHUNK][B * E];
__device__ __half g_Wh16[E * H];   // [k][n] fp16(W_h)

// ---------------------------------------------------------------------------
// Helpers
// ---------------------------------------------------------------------------
__device__ __forceinline__ uint32_t smem_u32(const void* p) {
    uint32_t a;
    asm("{ .reg .u64 t; cvta.to.shared.u64 t, %1; cvt.u32.u64 %0, t; }" : "=r"(a) : "l"(p));
    return a;
}
__device__ __forceinline__ void cp16(uint32_t dst, const void* src) {
    asm volatile("cp.async.cg.shared.global [%0], [%1], 16;" :: "r"(dst), "l"(src));
}
__device__ __forceinline__ void cp_commit() {
    asm volatile("cp.async.commit_group;" ::: "memory");
}
__device__ __forceinline__ void cp_wait1() {
    asm volatile("cp.async.wait_group 1;" ::: "memory");
}
__device__ __forceinline__ void ldsm_x4(uint32_t addr, uint32_t* r) {
    asm volatile("ldmatrix.sync.aligned.m8n8.x4.shared.b16 {%0,%1,%2,%3}, [%4];"
                 : "=r"(r[0]), "=r"(r[1]), "=r"(r[2]), "=r"(r[3]) : "r"(addr));
}
__device__ __forceinline__ void ldsm_x4_t(uint32_t addr, uint32_t* r) {
    asm volatile("ldmatrix.sync.aligned.m8n8.x4.trans.shared.b16 {%0,%1,%2,%3}, [%4];"
                 : "=r"(r[0]), "=r"(r[1]), "=r"(r[2]), "=r"(r[3]) : "r"(addr));
}
__device__ __forceinline__ void mma_fp16(float* c, const uint32_t* a, uint32_t b0, uint32_t b1) {
    asm volatile("mma.sync.aligned.m16n8k16.row.col.f32.f16.f16.f32 "
                 "{%0,%1,%2,%3}, {%4,%5,%6,%7}, {%8,%9}, {%0,%1,%2,%3};"
                 : "+f"(c[0]), "+f"(c[1]), "+f"(c[2]), "+f"(c[3])
                 : "r"(a[0]), "r"(a[1]), "r"(a[2]), "r"(a[3]), "r"(b0), "r"(b1));
}
__device__ __forceinline__ uint32_t pack_h2(float x, float y) {
    __half2 h = __floats2half2_rn(x, y);
    return *reinterpret_cast<uint32_t*>(&h);
}

// ---------------------------------------------------------------------------
// Kernel 0: W_h -> fp16 ([k][n] layout preserved)
// ---------------------------------------------------------------------------
__global__ __launch_bounds__(256) void conv_w_kernel(const float* __restrict__ Wh)
{
    int i = blockIdx.x * 256 + threadIdx.x;
    g_Wh16[i] = __float2half_rn(Wh[i]);
}

// ---------------------------------------------------------------------------
// Kernel 1: proj_dec (tiny)
// ---------------------------------------------------------------------------
__global__ __launch_bounds__(512) void proj_dec_kernel(
    const float* __restrict__ dec, const float* __restrict__ Wd)
{
    __shared__ float dsh[H];
    int b = blockIdx.x;
    int h = threadIdx.x;
    dsh[h] = dec[b * H + h];
    __syncthreads();
    float sum = 0.f;
#pragma unroll 8
    for (int d = 0; d < H; ++d)
        sum += dsh[d] * Wd[d * H + h];
    g_proj_dec[b * H + h] = sum;
}

// ---------------------------------------------------------------------------
// Kernel 2: scores via single-term fp16 mma.sync + fused tanh·v epilogue
// Block tile: 128(M) x 256(N), BK=32, 8 warps (2x4), warp tile 64x64.
// Grid: (2, 1024). blockIdx.x = n-pass (0/1), blockIdx.y = row block.
// ---------------------------------------------------------------------------
#define KSTEPS 32   // 1024 / 32

// Dynamic SMEM layout (bytes)
#define SW_BUF   0         // 3 x 16384
#define SA_BUF   49152     // 2 x 8192
#define S_PD     65536     // 256 f32
#define S_V      66560     // 256 f32
#define S_RED    67584     // 128*4 f32 = 2KB
#define SM_TOT   69632

__global__ void __launch_bounds__(256) scores_mma_kernel(
    const float* __restrict__ enc, const float* __restrict__ v)
{
    extern __shared__ char smem[];
    const uint32_t sb = smem_u32(smem);
    const int tid  = threadIdx.x;
    const int lane = tid & 31;
    const int warp = tid >> 5;
    const int wm   = warp >> 2;        // 0..1
    const int wn   = warp & 3;         // 0..3
    const int ny   = blockIdx.x;       // 0..1 (n-pass)
    const int row0 = blockIdx.y * 128;
    const int b    = row0 >> 11;       // S = 2048

    float* pd_sh = (float*)(smem + S_PD);
    float* v_sh  = (float*)(smem + S_V);
    float* red   = (float*)(smem + S_RED);
    pd_sh[tid] = g_proj_dec[b * H + ny * 256 + tid];
    v_sh[tid]  = v[ny * 256 + tid];

    // A (enc) load mapping: 2 threads per row, 16 k-elems each
    const int am = tid >> 1;           // 0..127
    const int ap = tid & 1;            // k half (0/1 -> 16 elems)
    const float* aptr = enc + (size_t)(row0 + am) * E + ap * 16;

    const __half* wbase = g_Wh16 + ny * 256;

    float c[4][8][4];
#pragma unroll
    for (int mt = 0; mt < 4; mt++)
#pragma unroll
        for (int j = 0; j < 8; j++)
#pragma unroll
            for (int q = 0; q < 4; q++) c[mt][j][q] = 0.f;

    uint4 pref[4];

    // ---- lambdas ----
    auto issueW = [&](int st) {
        uint32_t wb = sb + SW_BUF + (uint32_t)(st % 3) * 16384u;
        const __half* bh = wbase + (size_t)(st * 32) * H;
#pragma unroll
        for (int it = 0; it < 4; it++) {
            int idx = tid + it * 256;
            int k = idx >> 5;          // 0..31
            int g = idx & 31;          // 16B group (8 fp16)
            uint32_t off = (uint32_t)(k * 512 + ((g ^ (k & 7)) << 4));
            cp16(wb + off, bh + (size_t)k * H + g * 8);
        }
    };
    auto ldA = [&](int st) {
        const uint4* p = (const uint4*)(aptr + st * 32);
#pragma unroll
        for (int i = 0; i < 4; i++) pref[i] = p[i];
    };
    auto cvtStsA = [&](int st) {
        char* ab = smem + SA_BUF + (st & 1) * 8192;
#pragma unroll
        for (int i = 0; i < 4; i++) {
            float4 f = *(float4*)&pref[i];
            uint2 hv = make_uint2(pack_h2(f.x, f.y), pack_h2(f.z, f.w));
            int g = ap * 2 + (i >> 1);   // 16B group within 64B row
            uint32_t off = (uint32_t)(am * 64 + ((g ^ ((am >> 1) & 3)) << 4) + (i & 1) * 8);
            *(uint2*)(ab + off) = hv;
        }
    };
    auto doMMA = [&](int st) {
        uint32_t ab = sb + SA_BUF + (uint32_t)(st & 1) * 8192u;
        uint32_t wb = sb + SW_BUF + (uint32_t)(st % 3) * 16384u;
#pragma unroll
        for (int ks = 0; ks < 2; ks++) {
            uint32_t ah[4][4], bh[4][4];
            const int mrb = wm * 64 + (lane & 15);
            const int kg  = ks * 2 + (lane >> 4);
#pragma unroll
            for (int mt = 0; mt < 4; mt++) {
                int m = mrb + mt * 16;
                uint32_t off = (uint32_t)(m * 64 + ((kg ^ ((m >> 1) & 3)) << 4));
                ldsm_x4(ab + off, ah[mt]);
            }
            const int kr = ks * 16 + (lane & 7) + ((lane >> 3) & 1) * 8;
#pragma unroll
            for (int jj = 0; jj < 4; jj++) {
                int ng = wn * 8 + jj * 2 + (lane >> 4);
                uint32_t off = (uint32_t)(kr * 512 + ((ng ^ (kr & 7)) << 4));
                ldsm_x4_t(wb + off, bh[jj]);
            }
#pragma unroll
            for (int mt = 0; mt < 4; mt++)
#pragma unroll
                for (int j = 0; j < 8; j++) {
                    uint32_t b0 = bh[j >> 1][(j & 1) * 2];
                    uint32_t b1 = bh[j >> 1][(j & 1) * 2 + 1];
                    mma_fp16(c[mt][j], ah[mt], b0, b1);
                }
        }
    };

    // ---- prologue ----
    issueW(0); cp_commit();
    issueW(1); cp_commit();
    ldA(0);
    cvtStsA(0);
    cp_wait1();
    __syncthreads();

    // ---- main loop ----
    for (int i = 0; i < KSTEPS; i++) {
        const bool more = (i + 1 < KSTEPS);
        if (more) ldA(i + 1);
        if (i + 2 < KSTEPS) issueW(i + 2);
        cp_commit();                       // one group per iter (may be empty)
        doMMA(i);
        if (more) {
            cvtStsA(i + 1);
            cp_wait1();
            __syncthreads();
        }
    }

    // ---- epilogue: partial scores over this 256-n slice ----
    float p[4][2];
#pragma unroll
    for (int mt = 0; mt < 4; mt++) { p[mt][0] = 0.f; p[mt][1] = 0.f; }
#pragma unroll
    for (int mt = 0; mt < 4; mt++)
#pragma unroll
        for (int j = 0; j < 8; j++) {
            int nn = wn * 64 + j * 8 + ((lane & 3) << 1);
            float pd0 = pd_sh[nn], pd1 = pd_sh[nn + 1];
            float v0 = v_sh[nn], v1 = v_sh[nn + 1];
            p[mt][0] += tanhf(c[mt][j][0] + pd0) * v0 + tanhf(c[mt][j][1] + pd1) * v1;
            p[mt][1] += tanhf(c[mt][j][2] + pd0) * v0 + tanhf(c[mt][j][3] + pd1) * v1;
        }
#pragma unroll
    for (int mt = 0; mt < 4; mt++) {
        float p0 = p[mt][0], p1 = p[mt][1];
        p0 += __shfl_xor_sync(0xFFFFFFFF, p0, 1);
        p0 += __shfl_xor_sync(0xFFFFFFFF, p0, 2);
        p1 += __shfl_xor_sync(0xFFFFFFFF, p1, 1);
        p1 += __shfl_xor_sync(0xFFFFFFFF, p1, 2);
        if ((lane & 3) == 0) {
            int r = wm * 64 + mt * 16 + (lane >> 2);
            red[r * 4 + wn]       = p0;
            red[(r + 8) * 4 + wn] = p1;
        }
    }
    __syncthreads();
    if (tid < 128) {
        float s = red[tid * 4] + red[tid * 4 + 1] + red[tid * 4 + 2] + red[tid * 4 + 3];
        g_scores_part[ny][row0 + tid] = s;
    }
}

// ---------------------------------------------------------------------------
// Kernel 3: mask + softmax (sums the two n-pass partials)
// ---------------------------------------------------------------------------
__global__ __launch_bounds__(256) void softmax_kernel(
    const int* __restrict__ mask, float* __restrict__ attn)
{
    __shared__ float buf[S];
    __shared__ float redv[256];
    const int b = blockIdx.x;
    const int tid = threadIdx.x;

    float mx = -INFINITY;
    for (int s = tid; s < S; s += 256) {
        float sc = (mask[b * S + s] == 0)
                 ? -10000.0f
                 : (g_scores_part[0][b * S + s] + g_scores_part[1][b * S + s]);
        buf[s] = sc;
        mx = fmaxf(mx, sc);
    }
    redv[tid] = mx;
    __syncthreads();
    for (int st = 128; st > 0; st >>= 1) {
        if (tid < st) redv[tid] = fmaxf(redv[tid], redv[tid + st]);
        __syncthreads();
    }
    mx = redv[0];
    __syncthreads();

    float sum = 0.f;
    for (int s = tid; s < S; s += 256) {
        float e = __expf(buf[s] - mx);
        buf[s] = e;
        sum += e;
    }
    redv[tid] = sum;
    __syncthreads();
    for (int st = 128; st > 0; st >>= 1) {
        if (tid < st) redv[tid] += redv[tid + st];
        __syncthreads();
    }
    float inv = 1.0f / redv[0];
    for (int s = tid; s < S; s += 256)
        attn[b * S + s] = buf[s] * inv;
}

// ---------------------------------------------------------------------------
// Kernel 4: context partials. grid (B, NCHUNK).
// ---------------------------------------------------------------------------
__global__ __launch_bounds__(256) void context_part_kernel(
    const float* __restrict__ enc, const float* __restrict__ attn)
{
    __shared__ float w[S / NCHUNK];
    const int b = blockIdx.x;
    const int chunk = blockIdx.y;
    const int tid = threadIdx.x;
    const int s0 = chunk * (S / NCHUNK);

    for (int s = tid; s < S / NCHUNK; s += 256)
        w[s] = attn[b * S + s0 + s];
    __syncthreads();

    const float4* e4 = (const float4*)(enc + ((size_t)b * S + s0) * E);
    float4 c = make_float4(0.f, 0.f, 0.f, 0.f);
#pragma unroll 4
    for (int s = 0; s < S / NCHUNK; ++s) {
        float4 ev = e4[(size_t)s * (E / 4) + tid];
        float ww = w[s];
        c.x += ww * ev.x; c.y += ww * ev.y;
        c.z += ww * ev.z; c.w += ww * ev.w;
    }
    ((float4*)(&g_ctx_part[chunk][b * E]))[tid] = c;
}

// ---------------------------------------------------------------------------
// Kernel 5: reduce context partials into d_out.
// ---------------------------------------------------------------------------
__global__ __launch_bounds__(256) void context_reduce_kernel(float* __restrict__ ctx)
{
    const int b = blockIdx.x;
    const int tid = threadIdx.x;
    float4 c = make_float4(0.f, 0.f, 0.f, 0.f);
#pragma unroll
    for (int ch = 0; ch < NCHUNK; ++ch) {
        float4 p = ((const float4*)(&g_ctx_part[ch][b * E]))[tid];
        c.x += p.x; c.y += p.y; c.z += p.z; c.w += p.w;
    }
    ((float4*)(ctx + b * E))[tid] = c;
}

// ---------------------------------------------------------------------------
extern "C" void kernel_launch(void* const* d_in, const int* in_sizes, int n_in,
                              void* d_out, int out_size)
{
    const float* dec  = (const float*)d_in[0];  // (B, H)
    const float* enc  = (const float*)d_in[1];  // (B, S, 2H)
    const int*   mask = (const int*)  d_in[2];  // (B, S)
    const float* Wh   = (const float*)d_in[3];  // (2H, H)
    const float* Wd   = (const float*)d_in[4];  // (H, H)
    const float* v    = (const float*)d_in[5];  // (H,)

    float* out  = (float*)d_out;
    float* ctx  = out;             // (B, 2H)
    float* attn = out + B * E;     // (B, S)

    cudaFuncSetAttribute(scores_mma_kernel,
                         cudaFuncAttributeMaxDynamicSharedMemorySize, SM_TOT);

    conv_w_kernel<<<(E * H) / 256, 256>>>(Wh);
    proj_dec_kernel<<<B, H>>>(dec, Wd);
    dim3 gs(2, (B * S) / 128);
    scores_mma_kernel<<<gs, 256, SM_TOT>>>(enc, v);
    softmax_kernel<<<B, 256>>>(mask, attn);
    dim3 gctx(B, NCHUNK);
    context_part_kernel<<<gctx, 256>>>(enc, attn);
    context_reduce_kernel<<<B, 256>>>(ctx);
}

// round 5
// speedup vs baseline: 9.8821x; 1.1356x over previous
#include <cuda_runtime.h>
#include <cuda_bf16.h>
#include <cuda_fp16.h>
#include <cstdint>
#include <math.h>

#define B 64
#define S 2048
#define H 512
#define E 1024   // 2*H
#define NCHUNK 16

// ---------------------------------------------------------------------------
// Device scratch (allocation-free rule)
// ---------------------------------------------------------------------------
__device__ float g_proj_dec[B * H];
__device__ float g_scores_part[2][B * S];
__device__ float g_ctx_part[NCHUNK][B * E];
__device__ __half g_Wh16[E * H];   // [k][n] fp16(W_h)

// ---------------------------------------------------------------------------
// Helpers
// ---------------------------------------------------------------------------
__device__ __forceinline__ uint32_t smem_u32(const void* p) {
    uint32_t a;
    asm("{ .reg .u64 t; cvta.to.shared.u64 t, %1; cvt.u32.u64 %0, t; }" : "=r"(a) : "l"(p));
    return a;
}
__device__ __forceinline__ void cp16(uint32_t dst, const void* src) {
    asm volatile("cp.async.cg.shared.global [%0], [%1], 16;" :: "r"(dst), "l"(src));
}
__device__ __forceinline__ void cp_commit() {
    asm volatile("cp.async.commit_group;" ::: "memory");
}
__device__ __forceinline__ void cp_wait1() {
    asm volatile("cp.async.wait_group 1;" ::: "memory");
}
__device__ __forceinline__ void ldsm_x4(uint32_t addr, uint32_t* r) {
    asm volatile("ldmatrix.sync.aligned.m8n8.x4.shared.b16 {%0,%1,%2,%3}, [%4];"
                 : "=r"(r[0]), "=r"(r[1]), "=r"(r[2]), "=r"(r[3]) : "r"(addr));
}
__device__ __forceinline__ void ldsm_x4_t(uint32_t addr, uint32_t* r) {
    asm volatile("ldmatrix.sync.aligned.m8n8.x4.trans.shared.b16 {%0,%1,%2,%3}, [%4];"
                 : "=r"(r[0]), "=r"(r[1]), "=r"(r[2]), "=r"(r[3]) : "r"(addr));
}
__device__ __forceinline__ void mma_fp16(float* c, const uint32_t* a, uint32_t b0, uint32_t b1) {
    asm volatile("mma.sync.aligned.m16n8k16.row.col.f32.f16.f16.f32 "
                 "{%0,%1,%2,%3}, {%4,%5,%6,%7}, {%8,%9}, {%0,%1,%2,%3};"
                 : "+f"(c[0]), "+f"(c[1]), "+f"(c[2]), "+f"(c[3])
                 : "r"(a[0]), "r"(a[1]), "r"(a[2]), "r"(a[3]), "r"(b0), "r"(b1));
}
__device__ __forceinline__ uint32_t pack_h2(float x, float y) {
    __half2 h = __floats2half2_rn(x, y);
    return *reinterpret_cast<uint32_t*>(&h);
}

// ---------------------------------------------------------------------------
// Kernel 0: W_h -> fp16 ([k][n] layout preserved)
// ---------------------------------------------------------------------------
__global__ __launch_bounds__(256) void conv_w_kernel(const float* __restrict__ Wh)
{
    int i = blockIdx.x * 256 + threadIdx.x;
    g_Wh16[i] = __float2half_rn(Wh[i]);
}

// ---------------------------------------------------------------------------
// Kernel 1: proj_dec (tiny)
// ---------------------------------------------------------------------------
__global__ __launch_bounds__(512) void proj_dec_kernel(
    const float* __restrict__ dec, const float* __restrict__ Wd)
{
    __shared__ float dsh[H];
    int b = blockIdx.x;
    int h = threadIdx.x;
    dsh[h] = dec[b * H + h];
    __syncthreads();
    float sum = 0.f;
#pragma unroll 8
    for (int d = 0; d < H; ++d)
        sum += dsh[d] * Wd[d * H + h];
    g_proj_dec[b * H + h] = sum;
}

// ---------------------------------------------------------------------------
// Kernel 2: scores via single-term fp16 mma.sync + fused tanh·v epilogue
// Block tile: 128(M) x 256(N), BK=32, 16 warps (2x8), warp tile 64x32.
// Grid: (2, 1024). blockIdx.x = n-pass (0/1), blockIdx.y = row block.
// ---------------------------------------------------------------------------
#define KSTEPS 32   // 1024 / 32

// Dynamic SMEM layout (bytes)
#define SW_BUF   0         // 3 x 16384
#define SA_BUF   49152     // 2 x 8192
#define S_PD     65536     // 256 f32
#define S_V      66560     // 256 f32
#define S_RED    67584     // 128*8 f32 = 4KB
#define SM_TOT   71680

__global__ void __launch_bounds__(512, 1) scores_mma_kernel(
    const float* __restrict__ enc, const float* __restrict__ v)
{
    extern __shared__ char smem[];
    const uint32_t sb = smem_u32(smem);
    const int tid  = threadIdx.x;
    const int lane = tid & 31;
    const int warp = tid >> 5;
    const int wm   = warp >> 3;        // 0..1
    const int wn   = warp & 7;         // 0..7
    const int ny   = blockIdx.x;       // 0..1 (n-pass)
    const int row0 = blockIdx.y * 128;
    const int b    = row0 >> 11;       // S = 2048

    float* pd_sh = (float*)(smem + S_PD);
    float* v_sh  = (float*)(smem + S_V);
    float* red   = (float*)(smem + S_RED);
    if (tid < 256) {
        pd_sh[tid] = g_proj_dec[b * H + ny * 256 + tid];
        v_sh[tid]  = v[ny * 256 + tid];
    }

    // A (enc) load mapping: 4 threads per row, 8 k-elems (32B) each
    const int am = tid >> 2;           // 0..127
    const int ap = tid & 3;            // 16B group within 64B row
    const float* aptr = enc + (size_t)(row0 + am) * E + ap * 8;

    const __half* wbase = g_Wh16 + ny * 256;

    float c[4][4][4];
#pragma unroll
    for (int mt = 0; mt < 4; mt++)
#pragma unroll
        for (int j = 0; j < 4; j++)
#pragma unroll
            for (int q = 0; q < 4; q++) c[mt][j][q] = 0.f;

    uint4 pref[2];

    // ---- lambdas ----
    auto issueW = [&](int st) {
        uint32_t wb = sb + SW_BUF + (uint32_t)(st % 3) * 16384u;
        const __half* bh = wbase + (size_t)(st * 32) * H;
#pragma unroll
        for (int it = 0; it < 2; it++) {
            int idx = tid + it * 512;
            int k = idx >> 5;          // 0..31
            int g = idx & 31;          // 16B group (8 fp16)
            uint32_t off = (uint32_t)(k * 512 + ((g ^ (k & 7)) << 4));
            cp16(wb + off, bh + (size_t)k * H + g * 8);
        }
    };
    auto ldA = [&](int st) {
        const float4* p = (const float4*)(aptr + st * 32);
        pref[0] = *(const uint4*)(p);
        pref[1] = *(const uint4*)(p + 1);
    };
    auto cvtStsA = [&](int st) {
        char* ab = smem + SA_BUF + (st & 1) * 8192;
        float4 f0 = *(float4*)&pref[0];
        float4 f1 = *(float4*)&pref[1];
        uint4 hv;
        hv.x = pack_h2(f0.x, f0.y);
        hv.y = pack_h2(f0.z, f0.w);
        hv.z = pack_h2(f1.x, f1.y);
        hv.w = pack_h2(f1.z, f1.w);
        uint32_t off = (uint32_t)(am * 64 + ((ap ^ ((am >> 1) & 3)) << 4));
        *(uint4*)(ab + off) = hv;
    };
    auto doMMA = [&](int st) {
        uint32_t ab = sb + SA_BUF + (uint32_t)(st & 1) * 8192u;
        uint32_t wb = sb + SW_BUF + (uint32_t)(st % 3) * 16384u;
#pragma unroll
        for (int ks = 0; ks < 2; ks++) {
            uint32_t ah[4][4], bh[2][4];
            const int mrb = wm * 64 + (lane & 15);
            const int kg  = ks * 2 + (lane >> 4);
#pragma unroll
            for (int mt = 0; mt < 4; mt++) {
                int m = mrb + mt * 16;
                uint32_t off = (uint32_t)(m * 64 + ((kg ^ ((m >> 1) & 3)) << 4));
                ldsm_x4(ab + off, ah[mt]);
            }
            const int kr = ks * 16 + (lane & 7) + ((lane >> 3) & 1) * 8;
#pragma unroll
            for (int jj = 0; jj < 2; jj++) {
                int ng = wn * 4 + jj * 2 + (lane >> 4);
                uint32_t off = (uint32_t)(kr * 512 + ((ng ^ (kr & 7)) << 4));
                ldsm_x4_t(wb + off, bh[jj]);
            }
#pragma unroll
            for (int mt = 0; mt < 4; mt++)
#pragma unroll
                for (int j = 0; j < 4; j++) {
                    uint32_t b0 = bh[j >> 1][(j & 1) * 2];
                    uint32_t b1 = bh[j >> 1][(j & 1) * 2 + 1];
                    mma_fp16(c[mt][j], ah[mt], b0, b1);
                }
        }
    };

    // ---- prologue ----
    issueW(0); cp_commit();
    issueW(1); cp_commit();
    ldA(0);
    cvtStsA(0);
    cp_wait1();
    __syncthreads();

    // ---- main loop ----
    for (int i = 0; i < KSTEPS; i++) {
        const bool more = (i + 1 < KSTEPS);
        if (more) ldA(i + 1);
        if (i + 2 < KSTEPS) issueW(i + 2);
        cp_commit();                       // one group per iter (may be empty)
        doMMA(i);
        if (more) {
            cvtStsA(i + 1);
            cp_wait1();
            __syncthreads();
        }
    }

    // ---- epilogue: partial scores over this 256-n slice ----
    float p[4][2];
#pragma unroll
    for (int mt = 0; mt < 4; mt++) { p[mt][0] = 0.f; p[mt][1] = 0.f; }
#pragma unroll
    for (int mt = 0; mt < 4; mt++)
#pragma unroll
        for (int j = 0; j < 4; j++) {
            int nn = wn * 32 + j * 8 + ((lane & 3) << 1);
            float pd0 = pd_sh[nn], pd1 = pd_sh[nn + 1];
            float v0 = v_sh[nn], v1 = v_sh[nn + 1];
            p[mt][0] += tanhf(c[mt][j][0] + pd0) * v0 + tanhf(c[mt][j][1] + pd1) * v1;
            p[mt][1] += tanhf(c[mt][j][2] + pd0) * v0 + tanhf(c[mt][j][3] + pd1) * v1;
        }
#pragma unroll
    for (int mt = 0; mt < 4; mt++) {
        float p0 = p[mt][0], p1 = p[mt][1];
        p0 += __shfl_xor_sync(0xFFFFFFFF, p0, 1);
        p0 += __shfl_xor_sync(0xFFFFFFFF, p0, 2);
        p1 += __shfl_xor_sync(0xFFFFFFFF, p1, 1);
        p1 += __shfl_xor_sync(0xFFFFFFFF, p1, 2);
        if ((lane & 3) == 0) {
            int r = wm * 64 + mt * 16 + (lane >> 2);
            red[r * 8 + wn]       = p0;
            red[(r + 8) * 8 + wn] = p1;
        }
    }
    __syncthreads();
    if (tid < 128) {
        float s = 0.f;
#pragma unroll
        for (int t = 0; t < 8; t++) s += red[tid * 8 + t];
        g_scores_part[ny][row0 + tid] = s;
    }
}

// ---------------------------------------------------------------------------
// Kernel 3: mask + softmax (sums the two n-pass partials)
// ---------------------------------------------------------------------------
__global__ __launch_bounds__(256) void softmax_kernel(
    const int* __restrict__ mask, float* __restrict__ attn)
{
    __shared__ float buf[S];
    __shared__ float redv[256];
    const int b = blockIdx.x;
    const int tid = threadIdx.x;

    float mx = -INFINITY;
    for (int s = tid; s < S; s += 256) {
        float sc = (mask[b * S + s] == 0)
                 ? -10000.0f
                 : (g_scores_part[0][b * S + s] + g_scores_part[1][b * S + s]);
        buf[s] = sc;
        mx = fmaxf(mx, sc);
    }
    redv[tid] = mx;
    __syncthreads();
    for (int st = 128; st > 0; st >>= 1) {
        if (tid < st) redv[tid] = fmaxf(redv[tid], redv[tid + st]);
        __syncthreads();
    }
    mx = redv[0];
    __syncthreads();

    float sum = 0.f;
    for (int s = tid; s < S; s += 256) {
        float e = __expf(buf[s] - mx);
        buf[s] = e;
        sum += e;
    }
    redv[tid] = sum;
    __syncthreads();
    for (int st = 128; st > 0; st >>= 1) {
        if (tid < st) redv[tid] += redv[tid + st];
        __syncthreads();
    }
    float inv = 1.0f / redv[0];
    for (int s = tid; s < S; s += 256)
        attn[b * S + s] = buf[s] * inv;
}

// ---------------------------------------------------------------------------
// Kernel 4: context partials. grid (B, NCHUNK).
// ---------------------------------------------------------------------------
__global__ __launch_bounds__(256) void context_part_kernel(
    const float* __restrict__ enc, const float* __restrict__ attn)
{
    __shared__ float w[S / NCHUNK];
    const int b = blockIdx.x;
    const int chunk = blockIdx.y;
    const int tid = threadIdx.x;
    const int s0 = chunk * (S / NCHUNK);

    for (int s = tid; s < S / NCHUNK; s += 256)
        w[s] = attn[b * S + s0 + s];
    __syncthreads();

    const float4* e4 = (const float4*)(enc + ((size_t)b * S + s0) * E);
    float4 c = make_float4(0.f, 0.f, 0.f, 0.f);
#pragma unroll 4
    for (int s = 0; s < S / NCHUNK; ++s) {
        float4 ev = e4[(size_t)s * (E / 4) + tid];
        float ww = w[s];
        c.x += ww * ev.x; c.y += ww * ev.y;
        c.z += ww * ev.z; c.w += ww * ev.w;
    }
    ((float4*)(&g_ctx_part[chunk][b * E]))[tid] = c;
}

// ---------------------------------------------------------------------------
// Kernel 5: reduce context partials into d_out.
// ---------------------------------------------------------------------------
__global__ __launch_bounds__(256) void context_reduce_kernel(float* __restrict__ ctx)
{
    const int b = blockIdx.x;
    const int tid = threadIdx.x;
    float4 c = make_float4(0.f, 0.f, 0.f, 0.f);
#pragma unroll
    for (int ch = 0; ch < NCHUNK; ++ch) {
        float4 p = ((const float4*)(&g_ctx_part[ch][b * E]))[tid];
        c.x += p.x; c.y += p.y; c.z += p.z; c.w += p.w;
    }
    ((float4*)(ctx + b * E))[tid] = c;
}

// ---------------------------------------------------------------------------
extern "C" void kernel_launch(void* const* d_in, const int* in_sizes, int n_in,
                              void* d_out, int out_size)
{
    const float* dec  = (const float*)d_in[0];  // (B, H)
    const float* enc  = (const float*)d_in[1];  // (B, S, 2H)
    const int*   mask = (const int*)  d_in[2];  // (B, S)
    const float* Wh   = (const float*)d_in[3];  // (2H, H)
    const float* Wd   = (const float*)d_in[4];  // (H, H)
    const float* v    = (const float*)d_in[5];  // (H,)

    float* out  = (float*)d_out;
    float* ctx  = out;             // (B, 2H)
    float* attn = out + B * E;     // (B, S)

    cudaFuncSetAttribute(scores_mma_kernel,
                         cudaFuncAttributeMaxDynamicSharedMemorySize, SM_TOT);

    conv_w_kernel<<<(E * H) / 256, 256>>>(Wh);
    proj_dec_kernel<<<B, H>>>(dec, Wd);
    dim3 gs(2, (B * S) / 128);
    scores_mma_kernel<<<gs, 512, SM_TOT>>>(enc, v);
    softmax_kernel<<<B, 256>>>(mask, attn);
    dim3 gctx(B, NCHUNK);
    context_part_kernel<<<gctx, 256>>>(enc, attn);
    context_reduce_kernel<<<B, 256>>>(ctx);
}